// round 1
// baseline (speedup 1.0000x reference)
#include <cuda_runtime.h>
#include <math.h>

#define E_DIM   1024
#define NH      16
#define DH      64
#define BATCH   2
#define TSEQ    2048
#define MROWS   (BATCH * TSEQ)   // 4096

// Scratch (allocation-free rule: use __device__ globals)
__device__ float g_Q[MROWS * E_DIM];
__device__ float g_K[MROWS * E_DIM];
__device__ float g_V[MROWS * E_DIM];
__device__ float g_O[MROWS * E_DIM];

// ---------------------------------------------------------------------------
// GEMM (NT): C[M,N] = A[M,K] * B[N,K]^T   (all row-major)
// BM=128, BN=128, BK=16, 256 threads, 8x8 per thread.
// ---------------------------------------------------------------------------
#define BM 128
#define BN 128
#define BK 16
#define TM 8
#define TN 8

__global__ __launch_bounds__(256) void gemm_nt_kernel(
    const float* __restrict__ A, const float* __restrict__ B,
    float* __restrict__ C, int M, int N, int K)
{
    __shared__ float As[BK][BM];
    __shared__ float Bs[BK][BN];

    const int tx = threadIdx.x;        // 0..15  -> N dir
    const int ty = threadIdx.y;        // 0..15  -> M dir
    const int tid = ty * 16 + tx;
    const int row0 = blockIdx.y * BM;
    const int col0 = blockIdx.x * BN;

    float acc[TM][TN];
#pragma unroll
    for (int i = 0; i < TM; i++)
#pragma unroll
        for (int j = 0; j < TN; j++) acc[i][j] = 0.f;

    for (int k0 = 0; k0 < K; k0 += BK) {
        // Load A tile: BM x BK = 2048 floats = 512 float4, 256 threads -> 2 each
#pragma unroll
        for (int i = tid; i < BM * BK / 4; i += 256) {
            int r = i / (BK / 4);
            int c = (i % (BK / 4)) * 4;
            float4 v = *(const float4*)&A[(size_t)(row0 + r) * K + k0 + c];
            As[c + 0][r] = v.x; As[c + 1][r] = v.y;
            As[c + 2][r] = v.z; As[c + 3][r] = v.w;
        }
        // Load B tile: BN x BK
#pragma unroll
        for (int i = tid; i < BN * BK / 4; i += 256) {
            int r = i / (BK / 4);
            int c = (i % (BK / 4)) * 4;
            float4 v = *(const float4*)&B[(size_t)(col0 + r) * K + k0 + c];
            Bs[c + 0][r] = v.x; Bs[c + 1][r] = v.y;
            Bs[c + 2][r] = v.z; Bs[c + 3][r] = v.w;
        }
        __syncthreads();

#pragma unroll
        for (int kk = 0; kk < BK; kk++) {
            float a[TM], b[TN];
            *(float4*)&a[0] = *(const float4*)&As[kk][ty * TM + 0];
            *(float4*)&a[4] = *(const float4*)&As[kk][ty * TM + 4];
            *(float4*)&b[0] = *(const float4*)&Bs[kk][tx * TN + 0];
            *(float4*)&b[4] = *(const float4*)&Bs[kk][tx * TN + 4];
#pragma unroll
            for (int i = 0; i < TM; i++)
#pragma unroll
                for (int j = 0; j < TN; j++)
                    acc[i][j] += a[i] * b[j];
        }
        __syncthreads();
    }

    // Store 8x8 tile with float4
#pragma unroll
    for (int i = 0; i < TM; i++) {
        float* crow = &C[(size_t)(row0 + ty * TM + i) * N + col0 + tx * TN];
        *(float4*)&crow[0] = make_float4(acc[i][0], acc[i][1], acc[i][2], acc[i][3]);
        *(float4*)&crow[4] = make_float4(acc[i][4], acc[i][5], acc[i][6], acc[i][7]);
    }
}

// ---------------------------------------------------------------------------
// Causal flash attention, fp32. 1 thread = 1 query row.
// Block: 128 threads (BQ=128 query rows), one (b, h, q-tile) per block.
// KV streamed in tiles of BC=32 rows through shared memory.
// Q/K/V layouts: [B,T,E] row-major; head h occupies columns [h*DH, h*DH+64).
// ---------------------------------------------------------------------------
#define BQ 128
#define BC 32

__global__ __launch_bounds__(128) void attn_kernel(
    const float* __restrict__ Qm, const float* __restrict__ Km,
    const float* __restrict__ Vm, float* __restrict__ Om)
{
    __shared__ float Ks[BC][DH];
    __shared__ float Vs[BC][DH];

    const int b = blockIdx.z;
    const int h = blockIdx.y;
    const int q0 = blockIdx.x * BQ;
    const int tid = threadIdx.x;
    const int q = q0 + tid;

    // Load this thread's query row, pre-scaled by 1/sqrt(Dh)=0.125
    float qreg[DH];
    {
        const float* qrow = Qm + ((size_t)(b * TSEQ + q)) * E_DIM + h * DH;
#pragma unroll
        for (int d = 0; d < DH; d += 4) {
            float4 v = *(const float4*)&qrow[d];
            qreg[d + 0] = v.x * 0.125f;
            qreg[d + 1] = v.y * 0.125f;
            qreg[d + 2] = v.z * 0.125f;
            qreg[d + 3] = v.w * 0.125f;
        }
    }

    float m = -INFINITY, l = 0.f;
    float acc[DH];
#pragma unroll
    for (int d = 0; d < DH; d++) acc[d] = 0.f;

    const int kend = q0 + BQ;   // causal: keys [0, q0+BQ)
    for (int k0 = 0; k0 < kend; k0 += BC) {
        __syncthreads();   // previous tile fully consumed
        // Stage K/V tile: BC*DH = 2048 floats each; 128 threads, float4
#pragma unroll
        for (int i = tid; i < BC * (DH / 4); i += 128) {
            int r = i / (DH / 4);
            int c = (i % (DH / 4)) * 4;
            size_t base = ((size_t)(b * TSEQ + k0 + r)) * E_DIM + h * DH + c;
            *(float4*)&Ks[r][c] = *(const float4*)&Km[base];
            *(float4*)&Vs[r][c] = *(const float4*)&Vm[base];
        }
        __syncthreads();

        // Scores s[0..BC)
        float s[BC];
#pragma unroll 2
        for (int j = 0; j < BC; j += 4) {
            float s0 = 0.f, s1 = 0.f, s2 = 0.f, s3 = 0.f;
#pragma unroll
            for (int d = 0; d < DH; d += 4) {
                float4 k0v = *(const float4*)&Ks[j + 0][d];
                float4 k1v = *(const float4*)&Ks[j + 1][d];
                float4 k2v = *(const float4*)&Ks[j + 2][d];
                float4 k3v = *(const float4*)&Ks[j + 3][d];
                s0 += qreg[d] * k0v.x + qreg[d + 1] * k0v.y + qreg[d + 2] * k0v.z + qreg[d + 3] * k0v.w;
                s1 += qreg[d] * k1v.x + qreg[d + 1] * k1v.y + qreg[d + 2] * k1v.z + qreg[d + 3] * k1v.w;
                s2 += qreg[d] * k2v.x + qreg[d + 1] * k2v.y + qreg[d + 2] * k2v.z + qreg[d + 3] * k2v.w;
                s3 += qreg[d] * k3v.x + qreg[d + 1] * k3v.y + qreg[d + 2] * k3v.z + qreg[d + 3] * k3v.w;
            }
            s[j] = s0; s[j + 1] = s1; s[j + 2] = s2; s[j + 3] = s3;
        }

        // Causal mask + tile max
        float mnew = m;
#pragma unroll
        for (int j = 0; j < BC; j++) {
            if (k0 + j > q) s[j] = -INFINITY;
            mnew = fmaxf(mnew, s[j]);
        }

        float corr = __expf(m - mnew);   // first tile: exp(-inf)=0
        l *= corr;
#pragma unroll
        for (int d = 0; d < DH; d++) acc[d] *= corr;

#pragma unroll 4
        for (int j = 0; j < BC; j++) {
            float p = __expf(s[j] - mnew);
            l += p;
#pragma unroll
            for (int d = 0; d < DH; d += 4) {
                float4 v = *(const float4*)&Vs[j][d];
                acc[d + 0] += p * v.x;
                acc[d + 1] += p * v.y;
                acc[d + 2] += p * v.z;
                acc[d + 3] += p * v.w;
            }
        }
        m = mnew;
    }

    const float inv = 1.f / l;
    float* orow = Om + ((size_t)(b * TSEQ + q)) * E_DIM + h * DH;
#pragma unroll
    for (int d = 0; d < DH; d += 4) {
        float4 v = make_float4(acc[d] * inv, acc[d + 1] * inv,
                               acc[d + 2] * inv, acc[d + 3] * inv);
        *(float4*)&orow[d] = v;
    }
}

// ---------------------------------------------------------------------------
// Launch
// ---------------------------------------------------------------------------
extern "C" void kernel_launch(void* const* d_in, const int* in_sizes, int n_in,
                              void* d_out, int out_size)
{
    const float* q  = (const float*)d_in[0];
    const float* k  = (const float*)d_in[1];
    const float* v  = (const float*)d_in[2];
    const float* Wq = (const float*)d_in[3];
    const float* Wk = (const float*)d_in[4];
    const float* Wv = (const float*)d_in[5];
    const float* Wo = (const float*)d_in[6];
    float* out = (float*)d_out;

    float *Qp, *Kp, *Vp, *Op;
    cudaGetSymbolAddress((void**)&Qp, g_Q);
    cudaGetSymbolAddress((void**)&Kp, g_K);
    cudaGetSymbolAddress((void**)&Vp, g_V);
    cudaGetSymbolAddress((void**)&Op, g_O);

    dim3 gblk(16, 16);
    dim3 ggrid(E_DIM / BN, MROWS / BM);

    gemm_nt_kernel<<<ggrid, gblk>>>(q, Wq, Qp, MROWS, E_DIM, E_DIM);
    gemm_nt_kernel<<<ggrid, gblk>>>(k, Wk, Kp, MROWS, E_DIM, E_DIM);
    gemm_nt_kernel<<<ggrid, gblk>>>(v, Wv, Vp, MROWS, E_DIM, E_DIM);

    attn_kernel<<<dim3(TSEQ / BQ, NH, BATCH), 128>>>(Qp, Kp, Vp, Op);

    gemm_nt_kernel<<<ggrid, gblk>>>(Op, Wo, out, MROWS, E_DIM, E_DIM);
}

// round 2
// speedup vs baseline: 1.0094x; 1.0094x over previous
#include <cuda_runtime.h>
#include <math.h>

#define E_DIM   1024
#define NH      16
#define DH      64
#define BATCH   2
#define TSEQ    2048
#define MROWS   (BATCH * TSEQ)   // 4096

// Scratch (allocation-free rule: use __device__ globals)
__device__ float g_Q[MROWS * E_DIM];
__device__ float g_K[MROWS * E_DIM];
__device__ float g_V[MROWS * E_DIM];
__device__ float g_O[MROWS * E_DIM];

// ---------------------------------------------------------------------------
// Packed fp32x2 helpers (sm_103a packed-FP32 pipe; FFMA2 only via PTX)
// ---------------------------------------------------------------------------
__device__ __forceinline__ unsigned long long f2pk(float lo, float hi) {
    unsigned long long r;
    asm("mov.b64 %0, {%1, %2};" : "=l"(r) : "f"(lo), "f"(hi));
    return r;
}
__device__ __forceinline__ unsigned long long f2dup(float a) {
    unsigned long long r;
    asm("mov.b64 %0, {%1, %1};" : "=l"(r) : "f"(a));
    return r;
}
__device__ __forceinline__ unsigned long long ffma2(
    unsigned long long a, unsigned long long b, unsigned long long c) {
    unsigned long long d;
    asm("fma.rn.f32x2 %0, %1, %2, %3;" : "=l"(d) : "l"(a), "l"(b), "l"(c));
    return d;
}
__device__ __forceinline__ unsigned long long fmul2(
    unsigned long long a, unsigned long long b) {
    unsigned long long d;
    asm("mul.rn.f32x2 %0, %1, %2;" : "=l"(d) : "l"(a), "l"(b));
    return d;
}
__device__ __forceinline__ float2 f2up(unsigned long long v) {
    float lo, hi;
    asm("mov.b64 {%0, %1}, %2;" : "=f"(lo), "=f"(hi) : "l"(v));
    return make_float2(lo, hi);
}

// ---------------------------------------------------------------------------
// GEMM (NT): C[M,N] = A[M,K] * B[N,K]^T  (row-major), FFMA2 inner product.
// BM=128, BN=128, BK=16, 256 threads, 8x8 per thread.
// ---------------------------------------------------------------------------
#define BM 128
#define BN 128
#define BK 16
#define TM 8
#define TN 8

__global__ __launch_bounds__(256, 2) void gemm_nt_kernel(
    const float* __restrict__ A, const float* __restrict__ B,
    float* __restrict__ C, int M, int N, int K)
{
    __shared__ __align__(16) float As[BK][BM];
    __shared__ __align__(16) float Bs[BK][BN];

    const int tx = threadIdx.x;        // 0..15  -> N dir
    const int ty = threadIdx.y;        // 0..15  -> M dir
    const int tid = ty * 16 + tx;
    const int row0 = blockIdx.y * BM;
    const int col0 = blockIdx.x * BN;

    unsigned long long accp[TM][TN / 2];
#pragma unroll
    for (int i = 0; i < TM; i++)
#pragma unroll
        for (int j = 0; j < TN / 2; j++) accp[i][j] = 0ull;  // packed {0,0}

    for (int k0 = 0; k0 < K; k0 += BK) {
        // Load A tile: BM x BK floats, transpose into As[k][m]
#pragma unroll
        for (int i = tid; i < BM * BK / 4; i += 256) {
            int r = i / (BK / 4);
            int c = (i % (BK / 4)) * 4;
            float4 v = *(const float4*)&A[(size_t)(row0 + r) * K + k0 + c];
            As[c + 0][r] = v.x; As[c + 1][r] = v.y;
            As[c + 2][r] = v.z; As[c + 3][r] = v.w;
        }
        // Load B tile: BN x BK
#pragma unroll
        for (int i = tid; i < BN * BK / 4; i += 256) {
            int r = i / (BK / 4);
            int c = (i % (BK / 4)) * 4;
            float4 v = *(const float4*)&B[(size_t)(col0 + r) * K + k0 + c];
            Bs[c + 0][r] = v.x; Bs[c + 1][r] = v.y;
            Bs[c + 2][r] = v.z; Bs[c + 3][r] = v.w;
        }
        __syncthreads();

#pragma unroll
        for (int kk = 0; kk < BK; kk++) {
            float a[TM];
            *(float4*)&a[0] = *(const float4*)&As[kk][ty * TM + 0];
            *(float4*)&a[4] = *(const float4*)&As[kk][ty * TM + 4];
            // B pairs straight from smem (consecutive floats = packed pair)
            ulonglong2 b01 = *(const ulonglong2*)&Bs[kk][tx * TN + 0];
            ulonglong2 b23 = *(const ulonglong2*)&Bs[kk][tx * TN + 4];
            unsigned long long bp0 = b01.x, bp1 = b01.y, bp2 = b23.x, bp3 = b23.y;
#pragma unroll
            for (int i = 0; i < TM; i++) {
                unsigned long long ap = f2dup(a[i]);
                accp[i][0] = ffma2(ap, bp0, accp[i][0]);
                accp[i][1] = ffma2(ap, bp1, accp[i][1]);
                accp[i][2] = ffma2(ap, bp2, accp[i][2]);
                accp[i][3] = ffma2(ap, bp3, accp[i][3]);
            }
        }
        __syncthreads();
    }

#pragma unroll
    for (int i = 0; i < TM; i++) {
        float* crow = &C[(size_t)(row0 + ty * TM + i) * N + col0 + tx * TN];
        float2 u0 = f2up(accp[i][0]);
        float2 u1 = f2up(accp[i][1]);
        float2 u2 = f2up(accp[i][2]);
        float2 u3 = f2up(accp[i][3]);
        *(float4*)&crow[0] = make_float4(u0.x, u0.y, u1.x, u1.y);
        *(float4*)&crow[4] = make_float4(u2.x, u2.y, u3.x, u3.y);
    }
}

// ---------------------------------------------------------------------------
// Causal flash attention, fp32, FFMA2, split-D.
// 2 lanes per query row (lane <-> lane^16), each owns 32 of 64 dims.
// Block: 256 threads = 8 warps -> BQ=128 query rows per block.
// ---------------------------------------------------------------------------
#define BQ 128
#define BC 32

__global__ __launch_bounds__(256, 2) void attn_kernel(
    const float* __restrict__ Qm, const float* __restrict__ Km,
    const float* __restrict__ Vm, float* __restrict__ Om)
{
    __shared__ __align__(16) float Ks[BC][DH];
    __shared__ __align__(16) float Vs[BC][DH];

    const int b = blockIdx.z;
    const int h = blockIdx.y;
    const int q0 = blockIdx.x * BQ;
    const int tid = threadIdx.x;
    const int warp = tid >> 5;
    const int lane = tid & 31;
    const int qi = warp * 16 + (lane & 15);
    const int half = lane >> 4;
    const int q = q0 + qi;
    const int dbase = half * 32;         // this lane's 32-dim slice

    // Load my half of the query row, pre-scaled by 1/8, packed
    unsigned long long qp[16];
    {
        const float* qrow = Qm + ((size_t)(b * TSEQ + q)) * E_DIM + h * DH + dbase;
#pragma unroll
        for (int d = 0; d < 32; d += 4) {
            float4 v = *(const float4*)&qrow[d];
            qp[d / 2 + 0] = f2pk(v.x * 0.125f, v.y * 0.125f);
            qp[d / 2 + 1] = f2pk(v.z * 0.125f, v.w * 0.125f);
        }
    }

    float m = -INFINITY, l = 0.f;
    unsigned long long accp[16];
#pragma unroll
    for (int d = 0; d < 16; d++) accp[d] = 0ull;

    const int kend = q0 + BQ;   // causal: keys [0, q0+BQ)
    for (int k0 = 0; k0 < kend; k0 += BC) {
        __syncthreads();   // previous tile fully consumed
        // Stage K/V tile: BC*DH floats each; 256 threads, float4 -> 2 each
#pragma unroll
        for (int i = tid; i < BC * (DH / 4); i += 256) {
            int r = i / (DH / 4);
            int c = (i % (DH / 4)) * 4;
            size_t base = ((size_t)(b * TSEQ + k0 + r)) * E_DIM + h * DH + c;
            *(float4*)&Ks[r][c] = *(const float4*)&Km[base];
            *(float4*)&Vs[r][c] = *(const float4*)&Vm[base];
        }
        __syncthreads();

        // Scores: packed partial dot over my 32 dims, then lane-pair merge
        float s[BC];
#pragma unroll 2
        for (int j = 0; j < BC; j += 4) {
            unsigned long long s0 = 0ull, s1 = 0ull, s2 = 0ull, s3 = 0ull;
#pragma unroll
            for (int d = 0; d < 32; d += 4) {
                ulonglong2 k0v = *(const ulonglong2*)&Ks[j + 0][dbase + d];
                ulonglong2 k1v = *(const ulonglong2*)&Ks[j + 1][dbase + d];
                ulonglong2 k2v = *(const ulonglong2*)&Ks[j + 2][dbase + d];
                ulonglong2 k3v = *(const ulonglong2*)&Ks[j + 3][dbase + d];
                unsigned long long qa = qp[d / 2], qb = qp[d / 2 + 1];
                s0 = ffma2(qa, k0v.x, s0); s0 = ffma2(qb, k0v.y, s0);
                s1 = ffma2(qa, k1v.x, s1); s1 = ffma2(qb, k1v.y, s1);
                s2 = ffma2(qa, k2v.x, s2); s2 = ffma2(qb, k2v.y, s2);
                s3 = ffma2(qa, k3v.x, s3); s3 = ffma2(qb, k3v.y, s3);
            }
            float2 f0 = f2up(s0), f1 = f2up(s1), f2 = f2up(s2), f3 = f2up(s3);
            float v0 = f0.x + f0.y, v1 = f1.x + f1.y;
            float v2 = f2.x + f2.y, v3 = f3.x + f3.y;
            v0 += __shfl_xor_sync(0xFFFFFFFFu, v0, 16);
            v1 += __shfl_xor_sync(0xFFFFFFFFu, v1, 16);
            v2 += __shfl_xor_sync(0xFFFFFFFFu, v2, 16);
            v3 += __shfl_xor_sync(0xFFFFFFFFu, v3, 16);
            s[j] = v0; s[j + 1] = v1; s[j + 2] = v2; s[j + 3] = v3;
        }

        // Causal mask + tile max
        float mnew = m;
#pragma unroll
        for (int j = 0; j < BC; j++) {
            if (k0 + j > q) s[j] = -INFINITY;
            mnew = fmaxf(mnew, s[j]);
        }

        float corr = __expf(m - mnew);   // first tile: exp(-inf)=0
        l *= corr;
        {
            unsigned long long cp = f2dup(corr);
#pragma unroll
            for (int d = 0; d < 16; d++) accp[d] = fmul2(accp[d], cp);
        }

#pragma unroll 4
        for (int j = 0; j < BC; j++) {
            float p = __expf(s[j] - mnew);
            l += p;
            unsigned long long pd = f2dup(p);
#pragma unroll
            for (int d = 0; d < 32; d += 4) {
                ulonglong2 v = *(const ulonglong2*)&Vs[j][dbase + d];
                accp[d / 2 + 0] = ffma2(pd, v.x, accp[d / 2 + 0]);
                accp[d / 2 + 1] = ffma2(pd, v.y, accp[d / 2 + 1]);
            }
        }
        m = mnew;
    }

    const float inv = 1.f / l;
    float* orow = Om + ((size_t)(b * TSEQ + q)) * E_DIM + h * DH + dbase;
#pragma unroll
    for (int d = 0; d < 32; d += 4) {
        float2 u0 = f2up(accp[d / 2 + 0]);
        float2 u1 = f2up(accp[d / 2 + 1]);
        *(float4*)&orow[d] = make_float4(u0.x * inv, u0.y * inv,
                                         u1.x * inv, u1.y * inv);
    }
}

// ---------------------------------------------------------------------------
// Launch
// ---------------------------------------------------------------------------
extern "C" void kernel_launch(void* const* d_in, const int* in_sizes, int n_in,
                              void* d_out, int out_size)
{
    const float* q  = (const float*)d_in[0];
    const float* k  = (const float*)d_in[1];
    const float* v  = (const float*)d_in[2];
    const float* Wq = (const float*)d_in[3];
    const float* Wk = (const float*)d_in[4];
    const float* Wv = (const float*)d_in[5];
    const float* Wo = (const float*)d_in[6];
    float* out = (float*)d_out;

    float *Qp, *Kp, *Vp, *Op;
    cudaGetSymbolAddress((void**)&Qp, g_Q);
    cudaGetSymbolAddress((void**)&Kp, g_K);
    cudaGetSymbolAddress((void**)&Vp, g_V);
    cudaGetSymbolAddress((void**)&Op, g_O);

    dim3 gblk(16, 16);
    dim3 ggrid(E_DIM / BN, MROWS / BM);

    gemm_nt_kernel<<<ggrid, gblk>>>(q, Wq, Qp, MROWS, E_DIM, E_DIM);
    gemm_nt_kernel<<<ggrid, gblk>>>(k, Wk, Kp, MROWS, E_DIM, E_DIM);
    gemm_nt_kernel<<<ggrid, gblk>>>(v, Wv, Vp, MROWS, E_DIM, E_DIM);

    attn_kernel<<<dim3(TSEQ / BQ, NH, BATCH), 256>>>(Qp, Kp, Vp, Op);

    gemm_nt_kernel<<<ggrid, gblk>>>(Op, Wo, out, MROWS, E_DIM, E_DIM);
}

// round 5
// speedup vs baseline: 1.4316x; 1.4182x over previous
#include <cuda_runtime.h>
#include <cuda_bf16.h>
#include <cstdint>
#include <math.h>

#define E_DIM   1024
#define NH      16
#define DH      64
#define BATCH   2
#define TSEQ    2048
#define MROWS   (BATCH * TSEQ)   // 4096

// Scratch (allocation-free rule: use __device__ globals)
__device__ float g_Q[MROWS * E_DIM];
__device__ float g_K[MROWS * E_DIM];
__device__ float g_V[MROWS * E_DIM];
__device__ float g_O[MROWS * E_DIM];
__device__ __nv_bfloat16 g_xhi[MROWS * E_DIM];
__device__ __nv_bfloat16 g_xlo[MROWS * E_DIM];
__device__ __nv_bfloat16 g_whi[E_DIM * E_DIM];
__device__ __nv_bfloat16 g_wlo[E_DIM * E_DIM];

// ---------------------------------------------------------------------------
// Helpers
// ---------------------------------------------------------------------------
__device__ __forceinline__ uint32_t smem_u32(const void* p) {
    uint32_t a;
    asm("{ .reg .u64 t; cvta.to.shared.u64 t, %1; cvt.u32.u64 %0, t; }"
        : "=r"(a) : "l"(p));
    return a;
}

#define SW128(off) ((off) ^ (((off) >> 3) & 0x70))

__device__ __forceinline__ void ldsm_x4(uint32_t& r0, uint32_t& r1,
                                        uint32_t& r2, uint32_t& r3, uint32_t addr) {
    asm volatile("ldmatrix.sync.aligned.m8n8.x4.shared.b16 {%0,%1,%2,%3}, [%4];"
                 : "=r"(r0), "=r"(r1), "=r"(r2), "=r"(r3) : "r"(addr));
}
__device__ __forceinline__ void ldsm_x2(uint32_t& r0, uint32_t& r1, uint32_t addr) {
    asm volatile("ldmatrix.sync.aligned.m8n8.x2.shared.b16 {%0,%1}, [%2];"
                 : "=r"(r0), "=r"(r1) : "r"(addr));
}
__device__ __forceinline__ void mma_bf16(float* c, const uint32_t* a, const uint32_t* b) {
    asm volatile(
        "mma.sync.aligned.m16n8k16.row.col.f32.bf16.bf16.f32 "
        "{%0,%1,%2,%3}, {%4,%5,%6,%7}, {%8,%9}, {%0,%1,%2,%3};"
        : "+f"(c[0]), "+f"(c[1]), "+f"(c[2]), "+f"(c[3])
        : "r"(a[0]), "r"(a[1]), "r"(a[2]), "r"(a[3]), "r"(b[0]), "r"(b[1]));
}

// ---------------------------------------------------------------------------
// Split fp32 -> (hi, lo) bf16 pair.  x ~= hi + lo, |err| ~ 2^-17 |x|
// ---------------------------------------------------------------------------
__global__ __launch_bounds__(256) void split_bf16_kernel(
    const float* __restrict__ x, __nv_bfloat16* __restrict__ hi,
    __nv_bfloat16* __restrict__ lo, int n)
{
    int i = (blockIdx.x * 256 + threadIdx.x) * 4;
    if (i >= n) return;
    float4 v = *(const float4*)&x[i];
    __nv_bfloat16 h0 = __float2bfloat16(v.x);
    __nv_bfloat16 h1 = __float2bfloat16(v.y);
    __nv_bfloat16 h2 = __float2bfloat16(v.z);
    __nv_bfloat16 h3 = __float2bfloat16(v.w);
    __nv_bfloat16 l0 = __float2bfloat16(v.x - __bfloat162float(h0));
    __nv_bfloat16 l1 = __float2bfloat16(v.y - __bfloat162float(h1));
    __nv_bfloat16 l2 = __float2bfloat16(v.z - __bfloat162float(h2));
    __nv_bfloat16 l3 = __float2bfloat16(v.w - __bfloat162float(h3));
    ((__nv_bfloat162*)&hi[i])[0] = __nv_bfloat162(h0, h1);
    ((__nv_bfloat162*)&hi[i])[1] = __nv_bfloat162(h2, h3);
    ((__nv_bfloat162*)&lo[i])[0] = __nv_bfloat162(l0, l1);
    ((__nv_bfloat162*)&lo[i])[1] = __nv_bfloat162(l2, l3);
}

// ---------------------------------------------------------------------------
// HMMA GEMM (NT): C[M,1024] = (Ahi+Alo)[M,1024] * (Bhi+Blo)[1024,1024]^T
// 128x128 CTA tile, BK=64; 8 warps in 2(m) x 4(n); warp tile 64x32.
// mma.sync m16n8k16 bf16 -> fp32, 3 split combos (hh, hl, lh).
// Smem tiles SW128-swizzled (128B rows), conflict-free ldmatrix.
// ---------------------------------------------------------------------------
#define GK       1024
#define GN       1024
#define BKC      64                 // K per chunk
#define NCHUNKS  (GK / BKC)         // 16
#define TILE_B   (128 * 128)        // 16 KB per bf16 tile (128 rows x 128B)
#define SM_AHI   0
#define SM_ALO   (TILE_B)
#define SM_BHI   (2 * TILE_B)
#define SM_BLO   (3 * TILE_B)
#define SM_TOTAL (4 * TILE_B)       // 64 KB

__global__ __launch_bounds__(256) void mma_gemm_nt(
    const __nv_bfloat16* __restrict__ Ahi, const __nv_bfloat16* __restrict__ Alo,
    const __nv_bfloat16* __restrict__ Bhi, const __nv_bfloat16* __restrict__ Blo,
    float* __restrict__ C)
{
    extern __shared__ __align__(1024) char smem[];
    const uint32_t sbase = smem_u32(smem);
    const int tid    = threadIdx.x;
    const int wid    = tid >> 5;
    const int lane   = tid & 31;
    const int warp_m = wid >> 2;          // 0..1
    const int warp_n = wid & 3;           // 0..3
    const int row0   = blockIdx.y * 128;
    const int col0   = blockIdx.x * 128;

    float acc[4][4][4];
#pragma unroll
    for (int i = 0; i < 4; i++)
#pragma unroll
        for (int j = 0; j < 4; j++)
#pragma unroll
            for (int r = 0; r < 4; r++) acc[i][j][r] = 0.f;

    const __nv_bfloat16* srcA[2] = { Ahi + (size_t)row0 * GK, Alo + (size_t)row0 * GK };
    const __nv_bfloat16* srcB[2] = { Bhi + (size_t)col0 * GK, Blo + (size_t)col0 * GK };
    const uint32_t tileOff[4] = { SM_AHI, SM_ALO, SM_BHI, SM_BLO };

    // Per-thread ldmatrix row-offsets (bytes, pre-swizzle)
    uint32_t a_row[4], b_row[4];
#pragma unroll
    for (int mf = 0; mf < 4; mf++)
        a_row[mf] = (uint32_t)(warp_m * 64 + mf * 16 + (lane & 15)) * 128;
#pragma unroll
    for (int nf = 0; nf < 4; nf++)
        b_row[nf] = (uint32_t)(warp_n * 32 + nf * 8 + (lane & 7)) * 128;
    const uint32_t a_col = (uint32_t)(lane >> 4) * 16;        // bytes within k-step
    const uint32_t b_col = (uint32_t)((lane >> 3) & 1) * 16;  // bytes within k-step

    for (int c = 0; c < NCHUNKS; c++) {
        __syncthreads();
        // Fill 4 tiles (128 rows x 64 bf16) with SW128 swizzle; 16 float4/thread
#pragma unroll
        for (int i = tid; i < 4096; i += 256) {
            int t   = i >> 10;
            int idx = i & 1023;
            int r   = idx >> 3;
            int g   = idx & 7;
            const __nv_bfloat16* src =
                (t < 2 ? srcA[t] : srcB[t - 2]) + (size_t)r * GK + c * BKC + g * 8;
            float4 v = *(const float4*)src;
            uint32_t off = (uint32_t)(r * 128 + g * 16);
            *(float4*)(smem + tileOff[t] + SW128(off)) = v;
        }
        __syncthreads();

#pragma unroll
        for (int ks = 0; ks < 4; ks++) {
            const uint32_t kb = ks * 32;   // 16 bf16 = 32 bytes per k-step
            uint32_t ah[4][4], al[4][4], bh[4][2], bl[4][2];
#pragma unroll
            for (int mf = 0; mf < 4; mf++) {
                uint32_t off = SW128(a_row[mf] + kb + a_col);
                ldsm_x4(ah[mf][0], ah[mf][1], ah[mf][2], ah[mf][3],
                        sbase + SM_AHI + off);
                ldsm_x4(al[mf][0], al[mf][1], al[mf][2], al[mf][3],
                        sbase + SM_ALO + off);
            }
#pragma unroll
            for (int nf = 0; nf < 4; nf++) {
                uint32_t off = SW128(b_row[nf] + kb + b_col);
                ldsm_x2(bh[nf][0], bh[nf][1], sbase + SM_BHI + off);
                ldsm_x2(bl[nf][0], bl[nf][1], sbase + SM_BLO + off);
            }
#pragma unroll
            for (int mf = 0; mf < 4; mf++)
#pragma unroll
                for (int nf = 0; nf < 4; nf++) {
                    mma_bf16(acc[mf][nf], ah[mf], bh[nf]);
                    mma_bf16(acc[mf][nf], ah[mf], bl[nf]);
                    mma_bf16(acc[mf][nf], al[mf], bh[nf]);
                }
        }
    }

    // Epilogue: fragment c layout: c0,c1 -> (row lane/4, col 2*(lane%4));
    // c2,c3 -> row+8.
    const int rbase = row0 + warp_m * 64 + (lane >> 2);
    const int cbase = col0 + warp_n * 32 + 2 * (lane & 3);
#pragma unroll
    for (int mf = 0; mf < 4; mf++)
#pragma unroll
        for (int nf = 0; nf < 4; nf++) {
            float* p0 = &C[(size_t)(rbase + mf * 16) * GN + cbase + nf * 8];
            float* p1 = &C[(size_t)(rbase + mf * 16 + 8) * GN + cbase + nf * 8];
            *(float2*)p0 = make_float2(acc[mf][nf][0], acc[mf][nf][1]);
            *(float2*)p1 = make_float2(acc[mf][nf][2], acc[mf][nf][3]);
        }
}

// ---------------------------------------------------------------------------
// Packed fp32x2 helpers
// ---------------------------------------------------------------------------
__device__ __forceinline__ unsigned long long f2pk(float lo, float hi) {
    unsigned long long r;
    asm("mov.b64 %0, {%1, %2};" : "=l"(r) : "f"(lo), "f"(hi));
    return r;
}
__device__ __forceinline__ unsigned long long f2dup(float a) {
    unsigned long long r;
    asm("mov.b64 %0, {%1, %1};" : "=l"(r) : "f"(a));
    return r;
}
__device__ __forceinline__ unsigned long long ffma2(
    unsigned long long a, unsigned long long b, unsigned long long c) {
    unsigned long long d;
    asm("fma.rn.f32x2 %0, %1, %2, %3;" : "=l"(d) : "l"(a), "l"(b), "l"(c));
    return d;
}
__device__ __forceinline__ unsigned long long fmul2(
    unsigned long long a, unsigned long long b) {
    unsigned long long d;
    asm("mul.rn.f32x2 %0, %1, %2;" : "=l"(d) : "l"(a), "l"(b));
    return d;
}
__device__ __forceinline__ float2 f2up(unsigned long long v) {
    float lo, hi;
    asm("mov.b64 {%0, %1}, %2;" : "=f"(lo), "=f"(hi) : "l"(v));
    return make_float2(lo, hi);
}

// ---------------------------------------------------------------------------
// Causal flash attention, fp32, FFMA2, split-D (unchanged: 926us)
// ---------------------------------------------------------------------------
#define BQ 128
#define BC 32

__global__ __launch_bounds__(256, 2) void attn_kernel(
    const float* __restrict__ Qm, const float* __restrict__ Km,
    const float* __restrict__ Vm, float* __restrict__ Om)
{
    __shared__ __align__(16) float Ks[BC][DH];
    __shared__ __align__(16) float Vs[BC][DH];

    const int b = blockIdx.z;
    const int h = blockIdx.y;
    const int q0 = blockIdx.x * BQ;
    const int tid = threadIdx.x;
    const int warp = tid >> 5;
    const int lane = tid & 31;
    const int qi = warp * 16 + (lane & 15);
    const int half = lane >> 4;
    const int q = q0 + qi;
    const int dbase = half * 32;

    unsigned long long qp[16];
    {
        const float* qrow = Qm + ((size_t)(b * TSEQ + q)) * E_DIM + h * DH + dbase;
#pragma unroll
        for (int d = 0; d < 32; d += 4) {
            float4 v = *(const float4*)&qrow[d];
            qp[d / 2 + 0] = f2pk(v.x * 0.125f, v.y * 0.125f);
            qp[d / 2 + 1] = f2pk(v.z * 0.125f, v.w * 0.125f);
        }
    }

    float m = -INFINITY, l = 0.f;
    unsigned long long accp[16];
#pragma unroll
    for (int d = 0; d < 16; d++) accp[d] = 0ull;

    const int kend = q0 + BQ;
    for (int k0 = 0; k0 < kend; k0 += BC) {
        __syncthreads();
#pragma unroll
        for (int i = tid; i < BC * (DH / 4); i += 256) {
            int r = i / (DH / 4);
            int c = (i % (DH / 4)) * 4;
            size_t base = ((size_t)(b * TSEQ + k0 + r)) * E_DIM + h * DH + c;
            *(float4*)&Ks[r][c] = *(const float4*)&Km[base];
            *(float4*)&Vs[r][c] = *(const float4*)&Vm[base];
        }
        __syncthreads();

        float s[BC];
#pragma unroll 2
        for (int j = 0; j < BC; j += 4) {
            unsigned long long s0 = 0ull, s1 = 0ull, s2 = 0ull, s3 = 0ull;
#pragma unroll
            for (int d = 0; d < 32; d += 4) {
                ulonglong2 k0v = *(const ulonglong2*)&Ks[j + 0][dbase + d];
                ulonglong2 k1v = *(const ulonglong2*)&Ks[j + 1][dbase + d];
                ulonglong2 k2v = *(const ulonglong2*)&Ks[j + 2][dbase + d];
                ulonglong2 k3v = *(const ulonglong2*)&Ks[j + 3][dbase + d];
                unsigned long long qa = qp[d / 2], qb = qp[d / 2 + 1];
                s0 = ffma2(qa, k0v.x, s0); s0 = ffma2(qb, k0v.y, s0);
                s1 = ffma2(qa, k1v.x, s1); s1 = ffma2(qb, k1v.y, s1);
                s2 = ffma2(qa, k2v.x, s2); s2 = ffma2(qb, k2v.y, s2);
                s3 = ffma2(qa, k3v.x, s3); s3 = ffma2(qb, k3v.y, s3);
            }
            float2 f0 = f2up(s0), f1 = f2up(s1), f2 = f2up(s2), f3 = f2up(s3);
            float v0 = f0.x + f0.y, v1 = f1.x + f1.y;
            float v2 = f2.x + f2.y, v3 = f3.x + f3.y;
            v0 += __shfl_xor_sync(0xFFFFFFFFu, v0, 16);
            v1 += __shfl_xor_sync(0xFFFFFFFFu, v1, 16);
            v2 += __shfl_xor_sync(0xFFFFFFFFu, v2, 16);
            v3 += __shfl_xor_sync(0xFFFFFFFFu, v3, 16);
            s[j] = v0; s[j + 1] = v1; s[j + 2] = v2; s[j + 3] = v3;
        }

        float mnew = m;
#pragma unroll
        for (int j = 0; j < BC; j++) {
            if (k0 + j > q) s[j] = -INFINITY;
            mnew = fmaxf(mnew, s[j]);
        }

        float corr = __expf(m - mnew);
        l *= corr;
        {
            unsigned long long cp = f2dup(corr);
#pragma unroll
            for (int d = 0; d < 16; d++) accp[d] = fmul2(accp[d], cp);
        }

#pragma unroll 4
        for (int j = 0; j < BC; j++) {
            float p = __expf(s[j] - mnew);
            l += p;
            unsigned long long pd = f2dup(p);
#pragma unroll
            for (int d = 0; d < 32; d += 4) {
                ulonglong2 v = *(const ulonglong2*)&Vs[j][dbase + d];
                accp[d / 2 + 0] = ffma2(pd, v.x, accp[d / 2 + 0]);
                accp[d / 2 + 1] = ffma2(pd, v.y, accp[d / 2 + 1]);
            }
        }
        m = mnew;
    }

    const float inv = 1.f / l;
    float* orow = Om + ((size_t)(b * TSEQ + q)) * E_DIM + h * DH + dbase;
#pragma unroll
    for (int d = 0; d < 32; d += 4) {
        float2 u0 = f2up(accp[d / 2 + 0]);
        float2 u1 = f2up(accp[d / 2 + 1]);
        *(float4*)&orow[d] = make_float4(u0.x * inv, u0.y * inv,
                                         u1.x * inv, u1.y * inv);
    }
}

// ---------------------------------------------------------------------------
// Launch
// ---------------------------------------------------------------------------
extern "C" void kernel_launch(void* const* d_in, const int* in_sizes, int n_in,
                              void* d_out, int out_size)
{
    const float* q  = (const float*)d_in[0];
    const float* k  = (const float*)d_in[1];
    const float* v  = (const float*)d_in[2];
    const float* Wq = (const float*)d_in[3];
    const float* Wk = (const float*)d_in[4];
    const float* Wv = (const float*)d_in[5];
    const float* Wo = (const float*)d_in[6];
    float* out = (float*)d_out;

    float *Qp, *Kp, *Vp, *Op;
    __nv_bfloat16 *xhi, *xlo, *whi, *wlo;
    cudaGetSymbolAddress((void**)&Qp, g_Q);
    cudaGetSymbolAddress((void**)&Kp, g_K);
    cudaGetSymbolAddress((void**)&Vp, g_V);
    cudaGetSymbolAddress((void**)&Op, g_O);
    cudaGetSymbolAddress((void**)&xhi, g_xhi);
    cudaGetSymbolAddress((void**)&xlo, g_xlo);
    cudaGetSymbolAddress((void**)&whi, g_whi);
    cudaGetSymbolAddress((void**)&wlo, g_wlo);

    cudaFuncSetAttribute(mma_gemm_nt,
                         cudaFuncAttributeMaxDynamicSharedMemorySize, SM_TOTAL);

    const int NX = MROWS * E_DIM;          // 4M
    const int NW = E_DIM * E_DIM;          // 1M
    dim3 mgrid(GN / 128, MROWS / 128);     // (8, 32)

    // Q = q @ Wq^T
    split_bf16_kernel<<<NX / 1024, 256>>>(q, xhi, xlo, NX);
    split_bf16_kernel<<<NW / 1024, 256>>>(Wq, whi, wlo, NW);
    mma_gemm_nt<<<mgrid, 256, SM_TOTAL>>>(xhi, xlo, whi, wlo, Qp);
    // K
    split_bf16_kernel<<<NX / 1024, 256>>>(k, xhi, xlo, NX);
    split_bf16_kernel<<<NW / 1024, 256>>>(Wk, whi, wlo, NW);
    mma_gemm_nt<<<mgrid, 256, SM_TOTAL>>>(xhi, xlo, whi, wlo, Kp);
    // V
    split_bf16_kernel<<<NX / 1024, 256>>>(v, xhi, xlo, NX);
    split_bf16_kernel<<<NW / 1024, 256>>>(Wv, whi, wlo, NW);
    mma_gemm_nt<<<mgrid, 256, SM_TOTAL>>>(xhi, xlo, whi, wlo, Vp);

    attn_kernel<<<dim3(TSEQ / BQ, NH, BATCH), 256>>>(Qp, Kp, Vp, Op);

    // out = O @ Wo^T
    split_bf16_kernel<<<NX / 1024, 256>>>(Op, xhi, xlo, NX);
    split_bf16_kernel<<<NW / 1024, 256>>>(Wo, whi, wlo, NW);
    mma_gemm_nt<<<mgrid, 256, SM_TOTAL>>>(xhi, xlo, whi, wlo, out);
}

// round 6
// speedup vs baseline: 3.0258x; 2.1136x over previous
#include <cuda_runtime.h>
#include <cuda_bf16.h>
#include <cstdint>
#include <math.h>

#define E_DIM   1024
#define NH      16
#define DH      64
#define BATCH   2
#define TSEQ    2048
#define MROWS   (BATCH * TSEQ)   // 4096

// Scratch (allocation-free rule: use __device__ globals)
__device__ __nv_bfloat16 g_xhi[MROWS * E_DIM];
__device__ __nv_bfloat16 g_xlo[MROWS * E_DIM];
__device__ __nv_bfloat16 g_whi[E_DIM * E_DIM];
__device__ __nv_bfloat16 g_wlo[E_DIM * E_DIM];
__device__ __nv_bfloat16 g_Qhi[MROWS * E_DIM];
__device__ __nv_bfloat16 g_Qlo[MROWS * E_DIM];
__device__ __nv_bfloat16 g_Khi[MROWS * E_DIM];
__device__ __nv_bfloat16 g_Klo[MROWS * E_DIM];
__device__ __nv_bfloat16 g_Vhi[MROWS * E_DIM];
__device__ __nv_bfloat16 g_Vlo[MROWS * E_DIM];

// ---------------------------------------------------------------------------
// Helpers
// ---------------------------------------------------------------------------
__device__ __forceinline__ uint32_t smem_u32(const void* p) {
    uint32_t a;
    asm("{ .reg .u64 t; cvta.to.shared.u64 t, %1; cvt.u32.u64 %0, t; }"
        : "=r"(a) : "l"(p));
    return a;
}

#define SW128(off) ((off) ^ (((off) >> 3) & 0x70))

__device__ __forceinline__ void ldsm_x4(uint32_t& r0, uint32_t& r1,
                                        uint32_t& r2, uint32_t& r3, uint32_t addr) {
    asm volatile("ldmatrix.sync.aligned.m8n8.x4.shared.b16 {%0,%1,%2,%3}, [%4];"
                 : "=r"(r0), "=r"(r1), "=r"(r2), "=r"(r3) : "r"(addr));
}
__device__ __forceinline__ void ldsm_x4t(uint32_t& r0, uint32_t& r1,
                                         uint32_t& r2, uint32_t& r3, uint32_t addr) {
    asm volatile("ldmatrix.sync.aligned.m8n8.x4.trans.shared.b16 {%0,%1,%2,%3}, [%4];"
                 : "=r"(r0), "=r"(r1), "=r"(r2), "=r"(r3) : "r"(addr));
}
__device__ __forceinline__ void ldsm_x2(uint32_t& r0, uint32_t& r1, uint32_t addr) {
    asm volatile("ldmatrix.sync.aligned.m8n8.x2.shared.b16 {%0,%1}, [%2];"
                 : "=r"(r0), "=r"(r1) : "r"(addr));
}
__device__ __forceinline__ void mma_bf16(float* c, const uint32_t* a, const uint32_t* b) {
    asm volatile(
        "mma.sync.aligned.m16n8k16.row.col.f32.bf16.bf16.f32 "
        "{%0,%1,%2,%3}, {%4,%5,%6,%7}, {%8,%9}, {%0,%1,%2,%3};"
        : "+f"(c[0]), "+f"(c[1]), "+f"(c[2]), "+f"(c[3])
        : "r"(a[0]), "r"(a[1]), "r"(a[2]), "r"(a[3]), "r"(b[0]), "r"(b[1]));
}
// pack two fp32 as bf16x2 register: low16 = lo, high16 = hi
__device__ __forceinline__ uint32_t pk_bf16x2(float lo, float hi) {
    uint32_t r;
    asm("cvt.rn.bf16x2.f32 %0, %1, %2;" : "=r"(r) : "f"(hi), "f"(lo));
    return r;
}
__device__ __forceinline__ float bf16rt(float x) {
    return __bfloat162float(__float2bfloat16(x));
}

// ---------------------------------------------------------------------------
// Split fp32 -> (hi, lo) bf16 pair.  x ~= hi + lo, |err| ~ 2^-17 |x|
// ---------------------------------------------------------------------------
__global__ __launch_bounds__(256) void split_bf16_kernel(
    const float* __restrict__ x, __nv_bfloat16* __restrict__ hi,
    __nv_bfloat16* __restrict__ lo, int n)
{
    int i = (blockIdx.x * 256 + threadIdx.x) * 4;
    if (i >= n) return;
    float4 v = *(const float4*)&x[i];
    __nv_bfloat16 h0 = __float2bfloat16(v.x);
    __nv_bfloat16 h1 = __float2bfloat16(v.y);
    __nv_bfloat16 h2 = __float2bfloat16(v.z);
    __nv_bfloat16 h3 = __float2bfloat16(v.w);
    __nv_bfloat16 l0 = __float2bfloat16(v.x - __bfloat162float(h0));
    __nv_bfloat16 l1 = __float2bfloat16(v.y - __bfloat162float(h1));
    __nv_bfloat16 l2 = __float2bfloat16(v.z - __bfloat162float(h2));
    __nv_bfloat16 l3 = __float2bfloat16(v.w - __bfloat162float(h3));
    ((__nv_bfloat162*)&hi[i])[0] = __nv_bfloat162(h0, h1);
    ((__nv_bfloat162*)&hi[i])[1] = __nv_bfloat162(h2, h3);
    ((__nv_bfloat162*)&lo[i])[0] = __nv_bfloat162(l0, l1);
    ((__nv_bfloat162*)&lo[i])[1] = __nv_bfloat162(l2, l3);
}

// ---------------------------------------------------------------------------
// HMMA GEMM (NT): C = (Ahi+Alo) * (Bhi+Blo)^T, 128x128 CTA tile, BK=64.
// write_bf16=0 -> fp32 C;  write_bf16=1 -> bf16 hi/lo split outputs.
// ---------------------------------------------------------------------------
#define GK       1024
#define GN       1024
#define BKC      64
#define NCHUNKS  (GK / BKC)
#define TILE_B   (128 * 128)
#define SM_AHI   0
#define SM_ALO   (TILE_B)
#define SM_BHI   (2 * TILE_B)
#define SM_BLO   (3 * TILE_B)
#define SM_TOTAL (4 * TILE_B)       // 64 KB

__global__ __launch_bounds__(256) void mma_gemm_nt(
    const __nv_bfloat16* __restrict__ Ahi, const __nv_bfloat16* __restrict__ Alo,
    const __nv_bfloat16* __restrict__ Bhi, const __nv_bfloat16* __restrict__ Blo,
    float* __restrict__ C, __nv_bfloat16* __restrict__ Chi,
    __nv_bfloat16* __restrict__ Clo, int write_bf16)
{
    extern __shared__ __align__(1024) char smem[];
    const uint32_t sbase = smem_u32(smem);
    const int tid    = threadIdx.x;
    const int wid    = tid >> 5;
    const int lane   = tid & 31;
    const int warp_m = wid >> 2;
    const int warp_n = wid & 3;
    const int row0   = blockIdx.y * 128;
    const int col0   = blockIdx.x * 128;

    float acc[4][4][4];
#pragma unroll
    for (int i = 0; i < 4; i++)
#pragma unroll
        for (int j = 0; j < 4; j++)
#pragma unroll
            for (int r = 0; r < 4; r++) acc[i][j][r] = 0.f;

    const __nv_bfloat16* srcA[2] = { Ahi + (size_t)row0 * GK, Alo + (size_t)row0 * GK };
    const __nv_bfloat16* srcB[2] = { Bhi + (size_t)col0 * GK, Blo + (size_t)col0 * GK };
    const uint32_t tileOff[4] = { SM_AHI, SM_ALO, SM_BHI, SM_BLO };

    uint32_t a_row[4], b_row[4];
#pragma unroll
    for (int mf = 0; mf < 4; mf++)
        a_row[mf] = (uint32_t)(warp_m * 64 + mf * 16 + (lane & 15)) * 128;
#pragma unroll
    for (int nf = 0; nf < 4; nf++)
        b_row[nf] = (uint32_t)(warp_n * 32 + nf * 8 + (lane & 7)) * 128;
    const uint32_t a_col = (uint32_t)(lane >> 4) * 16;
    const uint32_t b_col = (uint32_t)((lane >> 3) & 1) * 16;

    for (int c = 0; c < NCHUNKS; c++) {
        __syncthreads();
#pragma unroll
        for (int i = tid; i < 4096; i += 256) {
            int t   = i >> 10;
            int idx = i & 1023;
            int r   = idx >> 3;
            int g   = idx & 7;
            const __nv_bfloat16* src =
                (t < 2 ? srcA[t] : srcB[t - 2]) + (size_t)r * GK + c * BKC + g * 8;
            float4 v = *(const float4*)src;
            uint32_t off = (uint32_t)(r * 128 + g * 16);
            *(float4*)(smem + tileOff[t] + SW128(off)) = v;
        }
        __syncthreads();

#pragma unroll
        for (int ks = 0; ks < 4; ks++) {
            const uint32_t kb = ks * 32;
            uint32_t ah[4][4], al[4][4], bh[4][2], bl[4][2];
#pragma unroll
            for (int mf = 0; mf < 4; mf++) {
                uint32_t off = SW128(a_row[mf] + kb + a_col);
                ldsm_x4(ah[mf][0], ah[mf][1], ah[mf][2], ah[mf][3],
                        sbase + SM_AHI + off);
                ldsm_x4(al[mf][0], al[mf][1], al[mf][2], al[mf][3],
                        sbase + SM_ALO + off);
            }
#pragma unroll
            for (int nf = 0; nf < 4; nf++) {
                uint32_t off = SW128(b_row[nf] + kb + b_col);
                ldsm_x2(bh[nf][0], bh[nf][1], sbase + SM_BHI + off);
                ldsm_x2(bl[nf][0], bl[nf][1], sbase + SM_BLO + off);
            }
#pragma unroll
            for (int mf = 0; mf < 4; mf++)
#pragma unroll
                for (int nf = 0; nf < 4; nf++) {
                    mma_bf16(acc[mf][nf], ah[mf], bh[nf]);
                    mma_bf16(acc[mf][nf], ah[mf], bl[nf]);
                    mma_bf16(acc[mf][nf], al[mf], bh[nf]);
                }
        }
    }

    const int rbase = row0 + warp_m * 64 + (lane >> 2);
    const int cbase = col0 + warp_n * 32 + 2 * (lane & 3);
    if (!write_bf16) {
#pragma unroll
        for (int mf = 0; mf < 4; mf++)
#pragma unroll
            for (int nf = 0; nf < 4; nf++) {
                float* p0 = &C[(size_t)(rbase + mf * 16) * GN + cbase + nf * 8];
                float* p1 = &C[(size_t)(rbase + mf * 16 + 8) * GN + cbase + nf * 8];
                *(float2*)p0 = make_float2(acc[mf][nf][0], acc[mf][nf][1]);
                *(float2*)p1 = make_float2(acc[mf][nf][2], acc[mf][nf][3]);
            }
    } else {
#pragma unroll
        for (int mf = 0; mf < 4; mf++)
#pragma unroll
            for (int nf = 0; nf < 4; nf++) {
                size_t o0 = (size_t)(rbase + mf * 16) * GN + cbase + nf * 8;
                size_t o1 = (size_t)(rbase + mf * 16 + 8) * GN + cbase + nf * 8;
                float x0 = acc[mf][nf][0], x1 = acc[mf][nf][1];
                float x2 = acc[mf][nf][2], x3 = acc[mf][nf][3];
                float h0 = bf16rt(x0), h1 = bf16rt(x1);
                float h2 = bf16rt(x2), h3 = bf16rt(x3);
                *(uint32_t*)&Chi[o0] = pk_bf16x2(h0, h1);
                *(uint32_t*)&Chi[o1] = pk_bf16x2(h2, h3);
                *(uint32_t*)&Clo[o0] = pk_bf16x2(x0 - h0, x1 - h1);
                *(uint32_t*)&Clo[o1] = pk_bf16x2(x2 - h2, x3 - h3);
            }
    }
}

// ---------------------------------------------------------------------------
// HMMA causal flash attention. CTA = (b, h, 128-row Q tile), 8 warps.
// Warp owns 16 Q rows. KV tiles of 64. Q/K/P/V all split hi/lo (3 combos).
// ---------------------------------------------------------------------------
#define AQ_HI 0
#define AQ_LO 16384
#define AK_HI 32768
#define AK_LO 40960
#define AV_HI 49152
#define AV_LO 57344
#define ASM_TOTAL 65536

__global__ __launch_bounds__(256, 1) void attn_mma_kernel(
    const __nv_bfloat16* __restrict__ Qhi, const __nv_bfloat16* __restrict__ Qlo,
    const __nv_bfloat16* __restrict__ Khi, const __nv_bfloat16* __restrict__ Klo,
    const __nv_bfloat16* __restrict__ Vhi, const __nv_bfloat16* __restrict__ Vlo,
    __nv_bfloat16* __restrict__ Ohi, __nv_bfloat16* __restrict__ Olo)
{
    extern __shared__ __align__(1024) char smem[];
    const uint32_t sbase = smem_u32(smem);
    const int b    = blockIdx.z;
    const int h    = blockIdx.y;
    const int q0   = blockIdx.x * 128;
    const int tid  = threadIdx.x;
    const int wid  = tid >> 5;
    const int lane = tid & 31;

    // --- Q fill (scaled by 1/sqrt(64) = 0.125, exact in bf16) ---
    {
        const __nv_bfloat162 sc = __nv_bfloat162(__float2bfloat16(0.125f),
                                                 __float2bfloat16(0.125f));
#pragma unroll
        for (int i = tid; i < 2048; i += 256) {
            int arr = i >> 10;
            int idx = i & 1023;
            int r   = idx >> 3;
            int g   = idx & 7;
            const __nv_bfloat16* src =
                (arr ? Qlo : Qhi) + (size_t)(b * TSEQ + q0 + r) * E_DIM + h * DH + g * 8;
            __nv_bfloat162 v[4];
            *(float4*)v = *(const float4*)src;
#pragma unroll
            for (int e = 0; e < 4; e++) v[e] = __hmul2(v[e], sc);
            uint32_t off = (uint32_t)(r * 128 + g * 16);
            *(float4*)(smem + (arr ? AQ_LO : AQ_HI) + SW128(off)) = *(float4*)v;
        }
    }
    __syncthreads();

    // --- Q fragments (per warp: rows wid*16..+16, all 64 d) ---
    uint32_t qh[4][4], ql[4][4];
#pragma unroll
    for (int j = 0; j < 4; j++) {
        uint32_t off = SW128((uint32_t)(wid * 16 + (lane & 15)) * 128
                             + j * 32 + (lane >> 4) * 16);
        ldsm_x4(qh[j][0], qh[j][1], qh[j][2], qh[j][3], sbase + AQ_HI + off);
        ldsm_x4(ql[j][0], ql[j][1], ql[j][2], ql[j][3], sbase + AQ_LO + off);
    }

    float o[8][4];
#pragma unroll
    for (int i = 0; i < 8; i++)
#pragma unroll
        for (int r = 0; r < 4; r++) o[i][r] = 0.f;
    float m0 = -INFINITY, m1 = -INFINITY, l0 = 0.f, l1 = 0.f;

    const int nfull  = q0 / 64;        // fully-unmasked tiles
    const int ntiles = nfull + 2;

    for (int t = 0; t < ntiles; t++) {
        const int k0 = t * 64;
        __syncthreads();
        // --- K/V tile fill ---
#pragma unroll
        for (int i = tid; i < 2048; i += 256) {
            int arr = i >> 9;          // 0:Khi 1:Klo 2:Vhi 3:Vlo
            int idx = i & 511;
            int r   = idx >> 3;
            int g   = idx & 7;
            const __nv_bfloat16* src =
                (arr == 0 ? Khi : arr == 1 ? Klo : arr == 2 ? Vhi : Vlo)
                + (size_t)(b * TSEQ + k0 + r) * E_DIM + h * DH + g * 8;
            float4 v = *(const float4*)src;
            uint32_t off = (uint32_t)(r * 128 + g * 16);
            *(float4*)(smem + AK_HI + arr * 8192 + SW128(off)) = v;
        }
        __syncthreads();

        // --- S = Q K^T (3 combos) ---
        float s[8][4];
#pragma unroll
        for (int i = 0; i < 8; i++)
#pragma unroll
            for (int r = 0; r < 4; r++) s[i][r] = 0.f;

#pragma unroll
        for (int ks = 0; ks < 4; ks++) {
            uint32_t bh[8][2], bl[8][2];
#pragma unroll
            for (int nb = 0; nb < 4; nb++) {
                uint32_t off = SW128((uint32_t)(nb * 16 + ((lane >> 4) << 3) + (lane & 7)) * 128
                                     + ks * 32 + ((lane >> 3) & 1) * 16);
                ldsm_x4(bh[2 * nb][0], bh[2 * nb][1], bh[2 * nb + 1][0], bh[2 * nb + 1][1],
                        sbase + AK_HI + off);
                ldsm_x4(bl[2 * nb][0], bl[2 * nb][1], bl[2 * nb + 1][0], bl[2 * nb + 1][1],
                        sbase + AK_LO + off);
            }
#pragma unroll
            for (int nf = 0; nf < 8; nf++) {
                mma_bf16(s[nf], qh[ks], bh[nf]);
                mma_bf16(s[nf], qh[ks], bl[nf]);
                mma_bf16(s[nf], ql[ks], bh[nf]);
            }
        }

        // --- causal mask (only the last two tiles can straddle) ---
        if (t >= nfull) {
            const int r0g = q0 + wid * 16 + (lane >> 2);
            const int r1g = r0g + 8;
            const int cb  = k0 + 2 * (lane & 3);
#pragma unroll
            for (int nf = 0; nf < 8; nf++) {
                int c0 = cb + nf * 8, c1 = c0 + 1;
                if (c0 > r0g) s[nf][0] = -INFINITY;
                if (c1 > r0g) s[nf][1] = -INFINITY;
                if (c0 > r1g) s[nf][2] = -INFINITY;
                if (c1 > r1g) s[nf][3] = -INFINITY;
            }
        }

        // --- online softmax ---
        float rm0 = s[0][0], rm1 = s[0][2];
#pragma unroll
        for (int nf = 0; nf < 8; nf++) {
            rm0 = fmaxf(rm0, fmaxf(s[nf][0], s[nf][1]));
            rm1 = fmaxf(rm1, fmaxf(s[nf][2], s[nf][3]));
        }
        rm0 = fmaxf(rm0, __shfl_xor_sync(0xFFFFFFFFu, rm0, 1));
        rm0 = fmaxf(rm0, __shfl_xor_sync(0xFFFFFFFFu, rm0, 2));
        rm1 = fmaxf(rm1, __shfl_xor_sync(0xFFFFFFFFu, rm1, 1));
        rm1 = fmaxf(rm1, __shfl_xor_sync(0xFFFFFFFFu, rm1, 2));
        float mn0 = fmaxf(m0, rm0), mn1 = fmaxf(m1, rm1);
        float cr0 = __expf(m0 - mn0), cr1 = __expf(m1 - mn1);
        m0 = mn0; m1 = mn1;
        l0 *= cr0; l1 *= cr1;
#pragma unroll
        for (int nf = 0; nf < 8; nf++) {
            o[nf][0] *= cr0; o[nf][1] *= cr0;
            o[nf][2] *= cr1; o[nf][3] *= cr1;
        }

        uint32_t uhi[8], ulo[8], whi[8], wlo[8];
#pragma unroll
        for (int nf = 0; nf < 8; nf++) {
            float p0 = __expf(s[nf][0] - mn0);
            float p1 = __expf(s[nf][1] - mn0);
            float p2 = __expf(s[nf][2] - mn1);
            float p3 = __expf(s[nf][3] - mn1);
            l0 += p0 + p1; l1 += p2 + p3;
            float h0 = bf16rt(p0), h1 = bf16rt(p1);
            float h2 = bf16rt(p2), h3 = bf16rt(p3);
            uhi[nf] = pk_bf16x2(h0, h1);
            whi[nf] = pk_bf16x2(h2, h3);
            ulo[nf] = pk_bf16x2(p0 - h0, p1 - h1);
            wlo[nf] = pk_bf16x2(p2 - h2, p3 - h3);
        }

        // --- O += P V (3 combos) ---
#pragma unroll
        for (int j = 0; j < 4; j++) {
            uint32_t pah[4] = { uhi[2 * j], whi[2 * j], uhi[2 * j + 1], whi[2 * j + 1] };
            uint32_t pal[4] = { ulo[2 * j], wlo[2 * j], ulo[2 * j + 1], wlo[2 * j + 1] };
            uint32_t vh[8][2], vl[8][2];
#pragma unroll
            for (int db = 0; db < 4; db++) {
                uint32_t off = SW128((uint32_t)(j * 16 + (lane & 15)) * 128
                                     + (db * 16 + ((lane >> 4) << 3)) * 2);
                ldsm_x4t(vh[2 * db][0], vh[2 * db][1], vh[2 * db + 1][0], vh[2 * db + 1][1],
                         sbase + AV_HI + off);
                ldsm_x4t(vl[2 * db][0], vl[2 * db][1], vl[2 * db + 1][0], vl[2 * db + 1][1],
                         sbase + AV_LO + off);
            }
#pragma unroll
            for (int nd = 0; nd < 8; nd++) {
                mma_bf16(o[nd], pah, vh[nd]);
                mma_bf16(o[nd], pah, vl[nd]);
                mma_bf16(o[nd], pal, vh[nd]);
            }
        }
    }

    // --- finalize: normalize + bf16 hi/lo split output ---
    l0 += __shfl_xor_sync(0xFFFFFFFFu, l0, 1);
    l0 += __shfl_xor_sync(0xFFFFFFFFu, l0, 2);
    l1 += __shfl_xor_sync(0xFFFFFFFFu, l1, 1);
    l1 += __shfl_xor_sync(0xFFFFFFFFu, l1, 2);
    const float inv0 = 1.f / l0, inv1 = 1.f / l1;
    const size_t gr0 = (size_t)(b * TSEQ + q0 + wid * 16 + (lane >> 2)) * E_DIM;
    const size_t gr1 = gr0 + 8 * E_DIM;
    const int cb = h * DH + 2 * (lane & 3);
#pragma unroll
    for (int nd = 0; nd < 8; nd++) {
        float x0 = o[nd][0] * inv0, x1 = o[nd][1] * inv0;
        float x2 = o[nd][2] * inv1, x3 = o[nd][3] * inv1;
        float h0 = bf16rt(x0), h1 = bf16rt(x1);
        float h2 = bf16rt(x2), h3 = bf16rt(x3);
        size_t c0 = gr0 + cb + nd * 8;
        size_t c1 = gr1 + cb + nd * 8;
        *(uint32_t*)&Ohi[c0] = pk_bf16x2(h0, h1);
        *(uint32_t*)&Ohi[c1] = pk_bf16x2(h2, h3);
        *(uint32_t*)&Olo[c0] = pk_bf16x2(x0 - h0, x1 - h1);
        *(uint32_t*)&Olo[c1] = pk_bf16x2(x2 - h2, x3 - h3);
    }
}

// ---------------------------------------------------------------------------
// Launch
// ---------------------------------------------------------------------------
extern "C" void kernel_launch(void* const* d_in, const int* in_sizes, int n_in,
                              void* d_out, int out_size)
{
    const float* q  = (const float*)d_in[0];
    const float* k  = (const float*)d_in[1];
    const float* v  = (const float*)d_in[2];
    const float* Wq = (const float*)d_in[3];
    const float* Wk = (const float*)d_in[4];
    const float* Wv = (const float*)d_in[5];
    const float* Wo = (const float*)d_in[6];
    float* out = (float*)d_out;

    __nv_bfloat16 *xhi, *xlo, *whi, *wlo;
    __nv_bfloat16 *Qhi, *Qlo, *Khi, *Klo, *Vhi, *Vlo;
    cudaGetSymbolAddress((void**)&xhi, g_xhi);
    cudaGetSymbolAddress((void**)&xlo, g_xlo);
    cudaGetSymbolAddress((void**)&whi, g_whi);
    cudaGetSymbolAddress((void**)&wlo, g_wlo);
    cudaGetSymbolAddress((void**)&Qhi, g_Qhi);
    cudaGetSymbolAddress((void**)&Qlo, g_Qlo);
    cudaGetSymbolAddress((void**)&Khi, g_Khi);
    cudaGetSymbolAddress((void**)&Klo, g_Klo);
    cudaGetSymbolAddress((void**)&Vhi, g_Vhi);
    cudaGetSymbolAddress((void**)&Vlo, g_Vlo);

    cudaFuncSetAttribute(mma_gemm_nt,
                         cudaFuncAttributeMaxDynamicSharedMemorySize, SM_TOTAL);
    cudaFuncSetAttribute(attn_mma_kernel,
                         cudaFuncAttributeMaxDynamicSharedMemorySize, ASM_TOTAL);

    const int NX = MROWS * E_DIM;
    const int NW = E_DIM * E_DIM;
    dim3 mgrid(GN / 128, MROWS / 128);

    // Projections -> bf16 hi/lo outputs directly
    split_bf16_kernel<<<NX / 1024, 256>>>(q, xhi, xlo, NX);
    split_bf16_kernel<<<NW / 1024, 256>>>(Wq, whi, wlo, NW);
    mma_gemm_nt<<<mgrid, 256, SM_TOTAL>>>(xhi, xlo, whi, wlo, nullptr, Qhi, Qlo, 1);

    split_bf16_kernel<<<NX / 1024, 256>>>(k, xhi, xlo, NX);
    split_bf16_kernel<<<NW / 1024, 256>>>(Wk, whi, wlo, NW);
    mma_gemm_nt<<<mgrid, 256, SM_TOTAL>>>(xhi, xlo, whi, wlo, nullptr, Khi, Klo, 1);

    split_bf16_kernel<<<NX / 1024, 256>>>(v, xhi, xlo, NX);
    split_bf16_kernel<<<NW / 1024, 256>>>(Wv, whi, wlo, NW);
    mma_gemm_nt<<<mgrid, 256, SM_TOTAL>>>(xhi, xlo, whi, wlo, nullptr, Vhi, Vlo, 1);

    // Attention: writes bf16 hi/lo into x buffers (free after V GEMM)
    attn_mma_kernel<<<dim3(TSEQ / 128, NH, BATCH), 256, ASM_TOTAL>>>(
        Qhi, Qlo, Khi, Klo, Vhi, Vlo, xhi, xlo);

    // Output projection -> fp32
    split_bf16_kernel<<<NW / 1024, 256>>>(Wo, whi, wlo, NW);
    mma_gemm_nt<<<mgrid, 256, SM_TOTAL>>>(xhi, xlo, whi, wlo, out, nullptr, nullptr, 0);
}

// round 10
// speedup vs baseline: 3.8684x; 1.2785x over previous
#include <cuda_runtime.h>
#include <cuda_bf16.h>
#include <cstdint>
#include <math.h>

#define E_DIM   1024
#define NH      16
#define DH      64
#define BATCH   2
#define TSEQ    2048
#define MROWS   (BATCH * TSEQ)   // 4096

// Scratch (allocation-free rule: use __device__ globals)
__device__ __nv_bfloat16 g_xhi[MROWS * E_DIM];
__device__ __nv_bfloat16 g_xlo[MROWS * E_DIM];
__device__ __nv_bfloat16 g_whi[E_DIM * E_DIM];
__device__ __nv_bfloat16 g_wlo[E_DIM * E_DIM];
__device__ __nv_bfloat16 g_Qhi[MROWS * E_DIM];
__device__ __nv_bfloat16 g_Qlo[MROWS * E_DIM];
__device__ __nv_bfloat16 g_Khi[MROWS * E_DIM];
__device__ __nv_bfloat16 g_Klo[MROWS * E_DIM];
__device__ __nv_bfloat16 g_Vhi[MROWS * E_DIM];
__device__ __nv_bfloat16 g_Vlo[MROWS * E_DIM];

// ---------------------------------------------------------------------------
// Helpers
// ---------------------------------------------------------------------------
__device__ __forceinline__ uint32_t smem_u32(const void* p) {
    uint32_t a;
    asm("{ .reg .u64 t; cvta.to.shared.u64 t, %1; cvt.u32.u64 %0, t; }"
        : "=r"(a) : "l"(p));
    return a;
}

#define SW128(off) ((off) ^ (((off) >> 3) & 0x70))

__device__ __forceinline__ void cp_async16(uint32_t dst, const void* src) {
    asm volatile("cp.async.cg.shared.global [%0], [%1], 16;"
                 :: "r"(dst), "l"(src) : "memory");
}
#define CP_COMMIT() asm volatile("cp.async.commit_group;" ::: "memory")
#define CP_WAIT(n)  asm volatile("cp.async.wait_group %0;" :: "n"(n) : "memory")

__device__ __forceinline__ void ldsm_x4(uint32_t& r0, uint32_t& r1,
                                        uint32_t& r2, uint32_t& r3, uint32_t addr) {
    asm volatile("ldmatrix.sync.aligned.m8n8.x4.shared.b16 {%0,%1,%2,%3}, [%4];"
                 : "=r"(r0), "=r"(r1), "=r"(r2), "=r"(r3) : "r"(addr));
}
__device__ __forceinline__ void ldsm_x4t(uint32_t& r0, uint32_t& r1,
                                         uint32_t& r2, uint32_t& r3, uint32_t addr) {
    asm volatile("ldmatrix.sync.aligned.m8n8.x4.trans.shared.b16 {%0,%1,%2,%3}, [%4];"
                 : "=r"(r0), "=r"(r1), "=r"(r2), "=r"(r3) : "r"(addr));
}
__device__ __forceinline__ void ldsm_x2(uint32_t& r0, uint32_t& r1, uint32_t addr) {
    asm volatile("ldmatrix.sync.aligned.m8n8.x2.shared.b16 {%0,%1}, [%2];"
                 : "=r"(r0), "=r"(r1) : "r"(addr));
}
__device__ __forceinline__ void mma_bf16(float* c, const uint32_t* a, const uint32_t* b) {
    asm volatile(
        "mma.sync.aligned.m16n8k16.row.col.f32.bf16.bf16.f32 "
        "{%0,%1,%2,%3}, {%4,%5,%6,%7}, {%8,%9}, {%0,%1,%2,%3};"
        : "+f"(c[0]), "+f"(c[1]), "+f"(c[2]), "+f"(c[3])
        : "r"(a[0]), "r"(a[1]), "r"(a[2]), "r"(a[3]), "r"(b[0]), "r"(b[1]));
}
__device__ __forceinline__ uint32_t pk_bf16x2(float lo, float hi) {
    uint32_t r;
    asm("cvt.rn.bf16x2.f32 %0, %1, %2;" : "=r"(r) : "f"(hi), "f"(lo));
    return r;
}
__device__ __forceinline__ float bf16rt(float x) {
    return __bfloat162float(__float2bfloat16(x));
}

// ---------------------------------------------------------------------------
// Split fp32 -> (hi, lo) bf16 pair.  x ~= hi + lo, |err| ~ 2^-17 |x|
// ---------------------------------------------------------------------------
__global__ __launch_bounds__(256) void split_bf16_kernel(
    const float* __restrict__ x, __nv_bfloat16* __restrict__ hi,
    __nv_bfloat16* __restrict__ lo, int n)
{
    int i = (blockIdx.x * 256 + threadIdx.x) * 4;
    if (i >= n) return;
    float4 v = *(const float4*)&x[i];
    __nv_bfloat16 h0 = __float2bfloat16(v.x);
    __nv_bfloat16 h1 = __float2bfloat16(v.y);
    __nv_bfloat16 h2 = __float2bfloat16(v.z);
    __nv_bfloat16 h3 = __float2bfloat16(v.w);
    __nv_bfloat16 l0 = __float2bfloat16(v.x - __bfloat162float(h0));
    __nv_bfloat16 l1 = __float2bfloat16(v.y - __bfloat162float(h1));
    __nv_bfloat16 l2 = __float2bfloat16(v.z - __bfloat162float(h2));
    __nv_bfloat16 l3 = __float2bfloat16(v.w - __bfloat162float(h3));
    ((__nv_bfloat162*)&hi[i])[0] = __nv_bfloat162(h0, h1);
    ((__nv_bfloat162*)&hi[i])[1] = __nv_bfloat162(h2, h3);
    ((__nv_bfloat162*)&lo[i])[0] = __nv_bfloat162(l0, l1);
    ((__nv_bfloat162*)&lo[i])[1] = __nv_bfloat162(l2, l3);
}

// ---------------------------------------------------------------------------
// HMMA GEMM (NT): C = (Ahi+Alo) * (Bhi+Blo)^T, 128x128 CTA tile, BK=64.
// cp.async double-buffered mainloop (2 x 64KB smem buffers).
// write_bf16=0 -> fp32 C;  write_bf16=1 -> bf16 hi/lo split outputs.
// ---------------------------------------------------------------------------
#define GK       1024
#define GN       1024
#define BKC      64
#define NCHUNKS  (GK / BKC)
#define TILE_B   (128 * 128)
#define SM_AHI   0
#define SM_ALO   (TILE_B)
#define SM_BHI   (2 * TILE_B)
#define SM_BLO   (3 * TILE_B)
#define BUF_B    (4 * TILE_B)       // 64 KB per buffer
#define SM_TOTAL (2 * BUF_B)        // 128 KB

__global__ __launch_bounds__(256, 1) void mma_gemm_nt(
    const __nv_bfloat16* __restrict__ Ahi, const __nv_bfloat16* __restrict__ Alo,
    const __nv_bfloat16* __restrict__ Bhi, const __nv_bfloat16* __restrict__ Blo,
    float* __restrict__ C, __nv_bfloat16* __restrict__ Chi,
    __nv_bfloat16* __restrict__ Clo, int write_bf16)
{
    extern __shared__ __align__(1024) char smem[];
    const uint32_t sbase = smem_u32(smem);
    const int tid    = threadIdx.x;
    const int wid    = tid >> 5;
    const int lane   = tid & 31;
    const int warp_m = wid >> 2;
    const int warp_n = wid & 3;
    const int row0   = blockIdx.y * 128;
    const int col0   = blockIdx.x * 128;

    float acc[4][4][4];
#pragma unroll
    for (int i = 0; i < 4; i++)
#pragma unroll
        for (int j = 0; j < 4; j++)
#pragma unroll
            for (int r = 0; r < 4; r++) acc[i][j][r] = 0.f;

    const __nv_bfloat16* srcA[2] = { Ahi + (size_t)row0 * GK, Alo + (size_t)row0 * GK };
    const __nv_bfloat16* srcB[2] = { Bhi + (size_t)col0 * GK, Blo + (size_t)col0 * GK };
    const uint32_t tileOff[4] = { SM_AHI, SM_ALO, SM_BHI, SM_BLO };

    uint32_t a_row[4], b_row[4];
#pragma unroll
    for (int mf = 0; mf < 4; mf++)
        a_row[mf] = (uint32_t)(warp_m * 64 + mf * 16 + (lane & 15)) * 128;
#pragma unroll
    for (int nf = 0; nf < 4; nf++)
        b_row[nf] = (uint32_t)(warp_n * 32 + nf * 8 + (lane & 7)) * 128;
    const uint32_t a_col = (uint32_t)(lane >> 4) * 16;
    const uint32_t b_col = (uint32_t)((lane >> 3) & 1) * 16;

    // issue async loads for chunk c into buffer buf
    auto load_chunk = [&](int c, int buf) {
        const uint32_t bb = sbase + buf * BUF_B;
#pragma unroll
        for (int i = tid; i < 4096; i += 256) {
            int t   = i >> 10;
            int idx = i & 1023;
            int r   = idx >> 3;
            int g   = idx & 7;
            const __nv_bfloat16* src =
                (t < 2 ? srcA[t] : srcB[t - 2]) + (size_t)r * GK + c * BKC + g * 8;
            uint32_t off = (uint32_t)(r * 128 + g * 16);
            cp_async16(bb + tileOff[t] + SW128(off), src);
        }
        CP_COMMIT();
    };

    load_chunk(0, 0);

    for (int c = 0; c < NCHUNKS; c++) {
        if (c + 1 < NCHUNKS) {
            load_chunk(c + 1, (c + 1) & 1);
            CP_WAIT(1);
        } else {
            CP_WAIT(0);
        }
        __syncthreads();

        const uint32_t bb = sbase + (c & 1) * BUF_B;
#pragma unroll
        for (int ks = 0; ks < 4; ks++) {
            const uint32_t kb = ks * 32;
            uint32_t ah[4][4], al[4][4], bh[4][2], bl[4][2];
#pragma unroll
            for (int mf = 0; mf < 4; mf++) {
                uint32_t off = SW128(a_row[mf] + kb + a_col);
                ldsm_x4(ah[mf][0], ah[mf][1], ah[mf][2], ah[mf][3], bb + SM_AHI + off);
                ldsm_x4(al[mf][0], al[mf][1], al[mf][2], al[mf][3], bb + SM_ALO + off);
            }
#pragma unroll
            for (int nf = 0; nf < 4; nf++) {
                uint32_t off = SW128(b_row[nf] + kb + b_col);
                ldsm_x2(bh[nf][0], bh[nf][1], bb + SM_BHI + off);
                ldsm_x2(bl[nf][0], bl[nf][1], bb + SM_BLO + off);
            }
#pragma unroll
            for (int mf = 0; mf < 4; mf++)
#pragma unroll
                for (int nf = 0; nf < 4; nf++) {
                    mma_bf16(acc[mf][nf], ah[mf], bh[nf]);
                    mma_bf16(acc[mf][nf], ah[mf], bl[nf]);
                    mma_bf16(acc[mf][nf], al[mf], bh[nf]);
                }
        }
        __syncthreads();
    }

    const int rbase = row0 + warp_m * 64 + (lane >> 2);
    const int cbase = col0 + warp_n * 32 + 2 * (lane & 3);
    if (!write_bf16) {
#pragma unroll
        for (int mf = 0; mf < 4; mf++)
#pragma unroll
            for (int nf = 0; nf < 4; nf++) {
                float* p0 = &C[(size_t)(rbase + mf * 16) * GN + cbase + nf * 8];
                float* p1 = &C[(size_t)(rbase + mf * 16 + 8) * GN + cbase + nf * 8];
                *(float2*)p0 = make_float2(acc[mf][nf][0], acc[mf][nf][1]);
                *(float2*)p1 = make_float2(acc[mf][nf][2], acc[mf][nf][3]);
            }
    } else {
#pragma unroll
        for (int mf = 0; mf < 4; mf++)
#pragma unroll
            for (int nf = 0; nf < 4; nf++) {
                size_t o0 = (size_t)(rbase + mf * 16) * GN + cbase + nf * 8;
                size_t o1 = (size_t)(rbase + mf * 16 + 8) * GN + cbase + nf * 8;
                float x0 = acc[mf][nf][0], x1 = acc[mf][nf][1];
                float x2 = acc[mf][nf][2], x3 = acc[mf][nf][3];
                float h0 = bf16rt(x0), h1 = bf16rt(x1);
                float h2 = bf16rt(x2), h3 = bf16rt(x3);
                *(uint32_t*)&Chi[o0] = pk_bf16x2(h0, h1);
                *(uint32_t*)&Chi[o1] = pk_bf16x2(h2, h3);
                *(uint32_t*)&Clo[o0] = pk_bf16x2(x0 - h0, x1 - h1);
                *(uint32_t*)&Clo[o1] = pk_bf16x2(x2 - h2, x3 - h3);
            }
    }
}

// ---------------------------------------------------------------------------
// HMMA causal flash attention, cp.async double-buffered KV.
// CTA = (b, h, 128-row Q tile), 8 warps, 16 Q rows/warp, KV tiles of 64.
// Smem: Q hi/lo 32KB + 2 x 32KB KV buffers = 96KB.
// ---------------------------------------------------------------------------
#define AQ_HI 0
#define AQ_LO 16384
#define AKV0  32768
#define KV_B  32768          // per-buffer: Khi 8K, Klo 8K, Vhi 8K, Vlo 8K
#define ASM_TOTAL (AKV0 + 2 * KV_B)   // 98304

__global__ __launch_bounds__(256, 1) void attn_mma_kernel(
    const __nv_bfloat16* __restrict__ Qhi, const __nv_bfloat16* __restrict__ Qlo,
    const __nv_bfloat16* __restrict__ Khi, const __nv_bfloat16* __restrict__ Klo,
    const __nv_bfloat16* __restrict__ Vhi, const __nv_bfloat16* __restrict__ Vlo,
    __nv_bfloat16* __restrict__ Ohi, __nv_bfloat16* __restrict__ Olo)
{
    extern __shared__ __align__(1024) char smem[];
    const uint32_t sbase = smem_u32(smem);
    const int b    = blockIdx.z;
    const int h    = blockIdx.y;
    const int q0   = blockIdx.x * 128;
    const int tid  = threadIdx.x;
    const int wid  = tid >> 5;
    const int lane = tid & 31;

    const int nfull  = q0 / 64;
    const int ntiles = nfull + 2;

    // issue async loads of KV tile t into buffer buf
    auto load_kv = [&](int t, int buf) {
        const int k0 = t * 64;
        const uint32_t bb = sbase + AKV0 + buf * KV_B;
#pragma unroll
        for (int i = tid; i < 2048; i += 256) {
            int arr = i >> 9;          // 0:Khi 1:Klo 2:Vhi 3:Vlo
            int idx = i & 511;
            int r   = idx >> 3;
            int g   = idx & 7;
            const __nv_bfloat16* src =
                (arr == 0 ? Khi : arr == 1 ? Klo : arr == 2 ? Vhi : Vlo)
                + (size_t)(b * TSEQ + k0 + r) * E_DIM + h * DH + g * 8;
            uint32_t off = (uint32_t)(r * 128 + g * 16);
            cp_async16(bb + arr * 8192 + SW128(off), src);
        }
        CP_COMMIT();
    };

    load_kv(0, 0);   // prefetch first KV tile (overlaps with Q fill below)

    // --- Q fill (unscaled; 1/8 applied to fp32 scores) ---
#pragma unroll
    for (int i = tid; i < 2048; i += 256) {
        int arr = i >> 10;
        int idx = i & 1023;
        int r   = idx >> 3;
        int g   = idx & 7;
        const __nv_bfloat16* src =
            (arr ? Qlo : Qhi) + (size_t)(b * TSEQ + q0 + r) * E_DIM + h * DH + g * 8;
        float4 v = *(const float4*)src;
        uint32_t off = (uint32_t)(r * 128 + g * 16);
        *(float4*)(smem + (arr ? AQ_LO : AQ_HI) + SW128(off)) = v;
    }
    __syncthreads();

    // --- Q fragments ---
    uint32_t qh[4][4], ql[4][4];
#pragma unroll
    for (int j = 0; j < 4; j++) {
        uint32_t off = SW128((uint32_t)(wid * 16 + (lane & 15)) * 128
                             + j * 32 + (lane >> 4) * 16);
        ldsm_x4(qh[j][0], qh[j][1], qh[j][2], qh[j][3], sbase + AQ_HI + off);
        ldsm_x4(ql[j][0], ql[j][1], ql[j][2], ql[j][3], sbase + AQ_LO + off);
    }

    float o[8][4];
#pragma unroll
    for (int i = 0; i < 8; i++)
#pragma unroll
        for (int r = 0; r < 4; r++) o[i][r] = 0.f;
    float m0 = -INFINITY, m1 = -INFINITY, l0 = 0.f, l1 = 0.f;

    for (int t = 0; t < ntiles; t++) {
        if (t + 1 < ntiles) {
            load_kv(t + 1, (t + 1) & 1);
            CP_WAIT(1);
        } else {
            CP_WAIT(0);
        }
        __syncthreads();

        const uint32_t bb = sbase + AKV0 + (t & 1) * KV_B;
        const int k0 = t * 64;

        // --- S = Q K^T (3 combos) ---
        float s[8][4];
#pragma unroll
        for (int i = 0; i < 8; i++)
#pragma unroll
            for (int r = 0; r < 4; r++) s[i][r] = 0.f;

#pragma unroll
        for (int ks = 0; ks < 4; ks++) {
            uint32_t bh[8][2], bl[8][2];
#pragma unroll
            for (int nb = 0; nb < 4; nb++) {
                uint32_t off = SW128((uint32_t)(nb * 16 + ((lane >> 4) << 3) + (lane & 7)) * 128
                                     + ks * 32 + ((lane >> 3) & 1) * 16);
                ldsm_x4(bh[2 * nb][0], bh[2 * nb][1], bh[2 * nb + 1][0], bh[2 * nb + 1][1],
                        bb + 0 + off);
                ldsm_x4(bl[2 * nb][0], bl[2 * nb][1], bl[2 * nb + 1][0], bl[2 * nb + 1][1],
                        bb + 8192 + off);
            }
#pragma unroll
            for (int nf = 0; nf < 8; nf++) {
                mma_bf16(s[nf], qh[ks], bh[nf]);
                mma_bf16(s[nf], qh[ks], bl[nf]);
                mma_bf16(s[nf], ql[ks], bh[nf]);
            }
        }
        // apply 1/sqrt(DH) = 0.125 (exact power of two)
#pragma unroll
        for (int nf = 0; nf < 8; nf++)
#pragma unroll
            for (int r = 0; r < 4; r++) s[nf][r] *= 0.125f;

        // --- causal mask ---
        if (t >= nfull) {
            const int r0g = q0 + wid * 16 + (lane >> 2);
            const int r1g = r0g + 8;
            const int cb  = k0 + 2 * (lane & 3);
#pragma unroll
            for (int nf = 0; nf < 8; nf++) {
                int c0 = cb + nf * 8, c1 = c0 + 1;
                if (c0 > r0g) s[nf][0] = -INFINITY;
                if (c1 > r0g) s[nf][1] = -INFINITY;
                if (c0 > r1g) s[nf][2] = -INFINITY;
                if (c1 > r1g) s[nf][3] = -INFINITY;
            }
        }

        // --- online softmax ---
        float rm0 = s[0][0], rm1 = s[0][2];
#pragma unroll
        for (int nf = 0; nf < 8; nf++) {
            rm0 = fmaxf(rm0, fmaxf(s[nf][0], s[nf][1]));
            rm1 = fmaxf(rm1, fmaxf(s[nf][2], s[nf][3]));
        }
        rm0 = fmaxf(rm0, __shfl_xor_sync(0xFFFFFFFFu, rm0, 1));
        rm0 = fmaxf(rm0, __shfl_xor_sync(0xFFFFFFFFu, rm0, 2));
        rm1 = fmaxf(rm1, __shfl_xor_sync(0xFFFFFFFFu, rm1, 1));
        rm1 = fmaxf(rm1, __shfl_xor_sync(0xFFFFFFFFu, rm1, 2));
        float mn0 = fmaxf(m0, rm0), mn1 = fmaxf(m1, rm1);
        float cr0 = __expf(m0 - mn0), cr1 = __expf(m1 - mn1);
        m0 = mn0; m1 = mn1;
        l0 *= cr0; l1 *= cr1;
#pragma unroll
        for (int nf = 0; nf < 8; nf++) {
            o[nf][0] *= cr0; o[nf][1] *= cr0;
            o[nf][2] *= cr1; o[nf][3] *= cr1;
        }

        uint32_t uhi[8], ulo[8], vhi2[8], vlo2[8];
#pragma unroll
        for (int nf = 0; nf < 8; nf++) {
            float p0 = __expf(s[nf][0] - mn0);
            float p1 = __expf(s[nf][1] - mn0);
            float p2 = __expf(s[nf][2] - mn1);
            float p3 = __expf(s[nf][3] - mn1);
            l0 += p0 + p1; l1 += p2 + p3;
            float h0 = bf16rt(p0), h1 = bf16rt(p1);
            float h2 = bf16rt(p2), h3 = bf16rt(p3);
            uhi[nf]  = pk_bf16x2(h0, h1);
            vhi2[nf] = pk_bf16x2(h2, h3);
            ulo[nf]  = pk_bf16x2(p0 - h0, p1 - h1);
            vlo2[nf] = pk_bf16x2(p2 - h2, p3 - h3);
        }

        // --- O += P V (3 combos) ---
#pragma unroll
        for (int j = 0; j < 4; j++) {
            uint32_t pah[4] = { uhi[2 * j], vhi2[2 * j], uhi[2 * j + 1], vhi2[2 * j + 1] };
            uint32_t pal[4] = { ulo[2 * j], vlo2[2 * j], ulo[2 * j + 1], vlo2[2 * j + 1] };
            uint32_t vh[8][2], vl[8][2];
#pragma unroll
            for (int db = 0; db < 4; db++) {
                uint32_t off = SW128((uint32_t)(j * 16 + (lane & 15)) * 128
                                     + (db * 16 + ((lane >> 4) << 3)) * 2);
                ldsm_x4t(vh[2 * db][0], vh[2 * db][1], vh[2 * db + 1][0], vh[2 * db + 1][1],
                         bb + 16384 + off);
                ldsm_x4t(vl[2 * db][0], vl[2 * db][1], vl[2 * db + 1][0], vl[2 * db + 1][1],
                         bb + 24576 + off);
            }
#pragma unroll
            for (int nd = 0; nd < 8; nd++) {
                mma_bf16(o[nd], pah, vh[nd]);
                mma_bf16(o[nd], pah, vl[nd]);
                mma_bf16(o[nd], pal, vh[nd]);
            }
        }
        __syncthreads();
    }

    // --- finalize ---
    l0 += __shfl_xor_sync(0xFFFFFFFFu, l0, 1);
    l0 += __shfl_xor_sync(0xFFFFFFFFu, l0, 2);
    l1 += __shfl_xor_sync(0xFFFFFFFFu, l1, 1);
    l1 += __shfl_xor_sync(0xFFFFFFFFu, l1, 2);
    const float inv0 = 1.f / l0, inv1 = 1.f / l1;
    const size_t gr0 = (size_t)(b * TSEQ + q0 + wid * 16 + (lane >> 2)) * E_DIM;
    const size_t gr1 = gr0 + 8 * E_DIM;
    const int cb = h * DH + 2 * (lane & 3);
#pragma unroll
    for (int nd = 0; nd < 8; nd++) {
        float x0 = o[nd][0] * inv0, x1 = o[nd][1] * inv0;
        float x2 = o[nd][2] * inv1, x3 = o[nd][3] * inv1;
        float h0 = bf16rt(x0), h1 = bf16rt(x1);
        float h2 = bf16rt(x2), h3 = bf16rt(x3);
        size_t c0 = gr0 + cb + nd * 8;
        size_t c1 = gr1 + cb + nd * 8;
        *(uint32_t*)&Ohi[c0] = pk_bf16x2(h0, h1);
        *(uint32_t*)&Ohi[c1] = pk_bf16x2(h2, h3);
        *(uint32_t*)&Olo[c0] = pk_bf16x2(x0 - h0, x1 - h1);
        *(uint32_t*)&Olo[c1] = pk_bf16x2(x2 - h2, x3 - h3);
    }
}

// ---------------------------------------------------------------------------
// Launch
// ---------------------------------------------------------------------------
extern "C" void kernel_launch(void* const* d_in, const int* in_sizes, int n_in,
                              void* d_out, int out_size)
{
    const float* q  = (const float*)d_in[0];
    const float* k  = (const float*)d_in[1];
    const float* v  = (const float*)d_in[2];
    const float* Wq = (const float*)d_in[3];
    const float* Wk = (const float*)d_in[4];
    const float* Wv = (const float*)d_in[5];
    const float* Wo = (const float*)d_in[6];
    float* out = (float*)d_out;

    __nv_bfloat16 *xhi, *xlo, *whi, *wlo;
    __nv_bfloat16 *Qhi, *Qlo, *Khi, *Klo, *Vhi, *Vlo;
    cudaGetSymbolAddress((void**)&xhi, g_xhi);
    cudaGetSymbolAddress((void**)&xlo, g_xlo);
    cudaGetSymbolAddress((void**)&whi, g_whi);
    cudaGetSymbolAddress((void**)&wlo, g_wlo);
    cudaGetSymbolAddress((void**)&Qhi, g_Qhi);
    cudaGetSymbolAddress((void**)&Qlo, g_Qlo);
    cudaGetSymbolAddress((void**)&Khi, g_Khi);
    cudaGetSymbolAddress((void**)&Klo, g_Klo);
    cudaGetSymbolAddress((void**)&Vhi, g_Vhi);
    cudaGetSymbolAddress((void**)&Vlo, g_Vlo);

    cudaFuncSetAttribute(mma_gemm_nt,
                         cudaFuncAttributeMaxDynamicSharedMemorySize, SM_TOTAL);
    cudaFuncSetAttribute(attn_mma_kernel,
                         cudaFuncAttributeMaxDynamicSharedMemorySize, ASM_TOTAL);

    const int NX = MROWS * E_DIM;
    const int NW = E_DIM * E_DIM;
    dim3 mgrid(GN / 128, MROWS / 128);

    // Projections -> bf16 hi/lo outputs directly
    split_bf16_kernel<<<NX / 1024, 256>>>(q, xhi, xlo, NX);
    split_bf16_kernel<<<NW / 1024, 256>>>(Wq, whi, wlo, NW);
    mma_gemm_nt<<<mgrid, 256, SM_TOTAL>>>(xhi, xlo, whi, wlo, nullptr, Qhi, Qlo, 1);

    split_bf16_kernel<<<NX / 1024, 256>>>(k, xhi, xlo, NX);
    split_bf16_kernel<<<NW / 1024, 256>>>(Wk, whi, wlo, NW);
    mma_gemm_nt<<<mgrid, 256, SM_TOTAL>>>(xhi, xlo, whi, wlo, nullptr, Khi, Klo, 1);

    split_bf16_kernel<<<NX / 1024, 256>>>(v, xhi, xlo, NX);
    split_bf16_kernel<<<NW / 1024, 256>>>(Wv, whi, wlo, NW);
    mma_gemm_nt<<<mgrid, 256, SM_TOTAL>>>(xhi, xlo, whi, wlo, nullptr, Vhi, Vlo, 1);

    // Attention: writes bf16 hi/lo into x buffers (free after V GEMM)
    attn_mma_kernel<<<dim3(TSEQ / 128, NH, BATCH), 256, ASM_TOTAL>>>(
        Qhi, Qlo, Khi, Klo, Vhi, Vlo, xhi, xlo);

    // Output projection -> fp32
    split_bf16_kernel<<<NW / 1024, 256>>>(Wo, whi, wlo, NW);
    mma_gemm_nt<<<mgrid, 256, SM_TOTAL>>>(xhi, xlo, whi, wlo, out, nullptr, nullptr, 0);
}